// round 12
// baseline (speedup 1.0000x reference)
#include <cuda_runtime.h>
#include <math.h>
#include <stdint.h>

#define B_ 8
#define L_ 512
#define S_ 128
#define D_ 256
#define M_ (B_*L_)
#define EPSV 1e-12f
#define TARGETW (1.0f/2000.0f)

// ---------------- scratch (static device memory; no allocation) ----------------
__device__ float g_Q[M_*D_];
__device__ float g_K[M_*D_];
__device__ float g_V[M_*D_];
__device__ float g_gate[M_];
__device__ float g_invQ[M_];
__device__ float g_invK[M_];

// ---------------- helpers ----------------
// NOTE: redux.sync.add.f32 is NOT supported by ptxas for sm_103 (verified R4).
__device__ __forceinline__ float wredsum(float v){
    v += __shfl_xor_sync(0xffffffffu, v, 16);
    v += __shfl_xor_sync(0xffffffffu, v, 8);
    v += __shfl_xor_sync(0xffffffffu, v, 4);
    v += __shfl_xor_sync(0xffffffffu, v, 2);
    v += __shfl_xor_sync(0xffffffffu, v, 1);
    return v;
}
__device__ __forceinline__ float dot4f(float4 a, float4 b, float acc){
    acc = fmaf(a.x, b.x, acc); acc = fmaf(a.y, b.y, acc);
    acc = fmaf(a.z, b.z, acc); acc = fmaf(a.w, b.w, acc);
    return acc;
}

// ---- packed f32x2 (sm_103a native; B300 quickref: FFMA2 via PTX fma.rn.f32x2) ----
typedef unsigned long long u64p;
__device__ __forceinline__ u64p fma2(u64p a, u64p b, u64p c){
    u64p d;
    asm("fma.rn.f32x2 %0, %1, %2, %3;" : "=l"(d) : "l"(a), "l"(b), "l"(c));
    return d;
}
__device__ __forceinline__ u64p mul2(u64p a, u64p b){
    u64p d;
    asm("mul.rn.f32x2 %0, %1, %2;" : "=l"(d) : "l"(a), "l"(b));
    return d;
}
__device__ __forceinline__ u64p pk1(float x){           // replicate scalar -> (x,x)
    u64p r;
    asm("mov.b64 %0, {%1, %1};" : "=l"(r) : "f"(x));
    return r;
}
__device__ __forceinline__ float hsum2(u64p v){         // lo+hi
    float lo, hi;
    asm("mov.b64 {%0, %1}, %2;" : "=f"(lo), "=f"(hi) : "l"(v));
    return lo + hi;
}
__device__ __forceinline__ void lds2(u64p& a, u64p& b, uint32_t addr){
    asm volatile("ld.shared.v2.u64 {%0, %1}, [%2];" : "=l"(a), "=l"(b) : "r"(addr));
}
__device__ __forceinline__ void sts2(uint32_t addr, u64p a, u64p b){
    asm volatile("st.shared.v2.u64 [%0], {%1, %2};" :: "r"(addr), "l"(a), "l"(b) : "memory");
}

// ---------------- QKV projection GEMM: C[m][n] = sum_k A[m][k]*W[n][k] + bias[n] ----------------
__global__ void gemm_nt(const float* __restrict__ A, const float* __restrict__ W,
                        const float* __restrict__ bias, float* __restrict__ C)
{
    constexpr int TM = 64, TN = 64, TK = 16, K = D_, N = D_;
    __shared__ __align__(16) float As[TK][TM];
    __shared__ __align__(16) float Bs[TK][TN];
    int bm = blockIdx.x * TM, bn = blockIdx.y * TN;
    int tid = threadIdx.x;
    int lrow = tid >> 2, lk = (tid & 3) * 4;
    int ty = (tid >> 4) << 2, tx = (tid & 15) << 2;
    float acc[4][4];
    #pragma unroll
    for (int i = 0; i < 4; i++)
        #pragma unroll
        for (int j = 0; j < 4; j++) acc[i][j] = 0.f;

    for (int k0 = 0; k0 < K; k0 += TK){
        float4 av = *(const float4*)(A + (size_t)(bm + lrow)*K + k0 + lk);
        float4 bv = *(const float4*)(W + (size_t)(bn + lrow)*K + k0 + lk);
        __syncthreads();
        As[lk+0][lrow]=av.x; As[lk+1][lrow]=av.y; As[lk+2][lrow]=av.z; As[lk+3][lrow]=av.w;
        Bs[lk+0][lrow]=bv.x; Bs[lk+1][lrow]=bv.y; Bs[lk+2][lrow]=bv.z; Bs[lk+3][lrow]=bv.w;
        __syncthreads();
        #pragma unroll
        for (int kk = 0; kk < TK; kk++){
            float4 a = *(const float4*)&As[kk][ty];
            float4 b = *(const float4*)&Bs[kk][tx];
            float ar[4] = {a.x, a.y, a.z, a.w};
            float br[4] = {b.x, b.y, b.z, b.w};
            #pragma unroll
            for (int i = 0; i < 4; i++)
                #pragma unroll
                for (int j = 0; j < 4; j++)
                    acc[i][j] = fmaf(ar[i], br[j], acc[i][j]);
        }
    }
    float4 b4 = *(const float4*)(bias + bn + tx);
    float bb[4] = {b4.x, b4.y, b4.z, b4.w};
    #pragma unroll
    for (int i = 0; i < 4; i++){
        float4 o;
        o.x = acc[i][0] + bb[0]; o.y = acc[i][1] + bb[1];
        o.z = acc[i][2] + bb[2]; o.w = acc[i][3] + bb[3];
        *(float4*)(C + (size_t)(bm + ty + i)*N + bn + tx) = o;
    }
}

// ---------------- gate: sigmoid(h . Wg + bg), one warp per row ----------------
__global__ void gate_kernel(const float* __restrict__ H, const float* __restrict__ Wg,
                            const float* __restrict__ bg)
{
    int gw = (blockIdx.x * blockDim.x + threadIdx.x) >> 5;
    int l = threadIdx.x & 31;
    if (gw >= M_) return;
    const float* h = H + (size_t)gw * D_;
    float s = 0.f;
    #pragma unroll 4
    for (int k = l; k < D_; k += 32) s = fmaf(h[k], Wg[k], s);
    s = wredsum(s);
    if (l == 0) g_gate[gw] = 1.f / (1.f + __expf(-(s + bg[0])));
}

// ---------------- 1/max(||q||,eps), 1/max(||k||,eps): one warp per row ----------------
__global__ void invnorm_kernel()
{
    int gw = (blockIdx.x * blockDim.x + threadIdx.x) >> 5;
    int l = threadIdx.x & 31;
    if (gw >= M_) return;
    const float* q = g_Q + (size_t)gw * D_;
    const float* k = g_K + (size_t)gw * D_;
    float sq = 0.f, sk = 0.f;
    #pragma unroll 4
    for (int i = l; i < D_; i += 32){
        float qv = q[i], kv = k[i];
        sq = fmaf(qv, qv, sq);
        sk = fmaf(kv, kv, sk);
    }
    sq = wredsum(sq); sk = wredsum(sk);
    if (l == 0){
        g_invQ[gw] = 1.f / fmaxf(sqrtf(sq), EPSV);
        g_invK[gw] = 1.f / fmaxf(sqrtf(sk), EPSV);
    }
}

// ---------------- sp scalar: mean_t (mean_b gate - target)^2 ----------------
__global__ void sp_kernel(float* __restrict__ out, int out_size)
{
    __shared__ float red[512];
    int t = threadIdx.x;   // L_ = 512 exactly
    float g = 0.f;
    #pragma unroll
    for (int b = 0; b < B_; b++) g += g_gate[b * L_ + t];
    g *= (1.f / (float)B_);
    float d = g - TARGETW;
    red[t] = d * d;
    __syncthreads();
    for (int off = 256; off > 0; off >>= 1){
        if (t < off) red[t] += red[t + off];
        __syncthreads();
    }
    if (t == 0 && out_size > M_ * D_) out[M_ * D_] = red[0] * (1.f / (float)L_);
}

// ---------------- persistent recurrence: one CTA per batch, mem in smem ----------------
// v2: packed f32x2 arithmetic in phase C; single-warp softmax fused with read_v
// writeout (2 barriers/step instead of 3).
__global__ void __launch_bounds__(512, 1) recur_kernel(
    const float* __restrict__ Minit, const float* __restrict__ masks,
    float* __restrict__ out)
{
    constexpr int NW = 16;           // warps
    constexpr int RPW = S_ / NW;     // rows per warp = 8
    extern __shared__ __align__(16) float sm[];
    float* mem   = sm;                       // S_*D_
    float* dotq  = sm + S_*D_;               // S_
    float* dotk  = dotq + S_;
    float* nrm   = dotk + S_;
    float* rw    = nrm + S_;
    float* pc    = rw + S_;
    float* rc    = pc + S_;
    float* readp = rc + S_;                  // NW*D_

    int b = blockIdx.x;
    int tid = threadIdx.x, w = tid >> 5, l = tid & 31;
    float4* mem4 = (float4*)mem;

    uint32_t memb   = (uint32_t)__cvta_generic_to_shared(mem);
    uint32_t readpb = (uint32_t)__cvta_generic_to_shared(readp);

    // load initial memory
    const float4* M4 = (const float4*)(Minit + (size_t)b * S_ * D_);
    for (int i = tid; i < S_ * D_ / 4; i += 512) mem4[i] = M4[i];
    __syncthreads();

    // prologue: dots/norms of initial mem against raw q0, k0
    {
        const float4* Qp = (const float4*)(g_Q + (size_t)(b * L_) * D_);
        const float4* Kp = (const float4*)(g_K + (size_t)(b * L_) * D_);
        float4 q0 = Qp[l], q1 = Qp[32 + l], k0 = Kp[l], k1 = Kp[32 + l];
        #pragma unroll
        for (int i = 0; i < RPW; i++){
            int s = w * RPW + i;
            float4 m0 = mem4[s*64 + l], m1 = mem4[s*64 + 32 + l];
            float dq = dot4f(m0, q0, dot4f(m1, q1, 0.f));
            float dk = dot4f(m0, k0, dot4f(m1, k1, 0.f));
            float nn = dot4f(m0, m0, dot4f(m1, m1, 0.f));
            dq = wredsum(dq); dk = wredsum(dk); nn = wredsum(nn);
            if (l == 0){ dotq[s] = dq; dotk[s] = dk; nrm[s] = nn; }
        }
    }
    __syncthreads();

    for (int t = 0; t < L_; t++){
        // ---- phase AB: warp 0 does the ENTIRE softmax (no cross-warp exchange);
        //      warps 8-15 write read_v of step t-1 to gmem.
        if (w == 0){
            float gt   = g_gate[b*L_ + t];
            float mval = masks[b*L_ + t];
            float gm   = gt * mval;
            float iQ   = g_invQ[b*L_ + t];
            float iK   = g_invK[b*L_ + t];
            float eqv[4], ewv[4];
            float peq = 0.f, pew = 0.f;
            #pragma unroll
            for (int j = 0; j < 4; j++){
                int s = l + 32*j;
                float inv = 1.f / fmaxf(sqrtf(nrm[s]), EPSV);
                eqv[j] = __expf(2.f * dotq[s] * (iQ * inv));
                ewv[j] = __expf(2.f * dotk[s] * (iK * inv));
                peq += eqv[j]; pew += ewv[j];
            }
            float SQ = wredsum(peq);       // sum over all 128 s within one warp
            float SW = wredsum(pew);
            float rSQ = 1.f / SQ, rSW = 1.f / SW;
            #pragma unroll
            for (int j = 0; j < 4; j++){
                int s = l + 32*j;
                rw[s] = eqv[j] * rSQ;
                float rcv = gm * (ewv[j] * rSW);   // = mask*gate*softmax_w
                rc[s] = rcv;
                pc[s] = mval - rcv;                // = mask*(1 - gate*softmax_w)
            }
        } else if (tid >= 256 && t > 0){
            int d = tid - 256;                     // 256 threads cover D_
            float acc = 0.f;
            #pragma unroll
            for (int j = 0; j < NW; j++) acc += readp[j*D_ + d];
            out[(size_t)(b*L_ + (t-1))*D_ + d] = acc;
        }
        __syncthreads();

        // ---- phase C (all warps, packed f32x2): read_v partials (old mem),
        //      write update + mask, dots/norms of NEW mem vs raw q_{t+1}, k_{t+1}
        {
            int tn = (t + 1 < L_) ? (t + 1) : (L_ - 1);
            const ulonglong2* Qp = (const ulonglong2*)(g_Q + (size_t)(b*L_ + tn)*D_);
            const ulonglong2* Kp = (const ulonglong2*)(g_K + (size_t)(b*L_ + tn)*D_);
            const ulonglong2* Vp = (const ulonglong2*)(g_V + (size_t)(b*L_ + t )*D_);
            ulonglong2 qA = Qp[l], qB = Qp[32 + l];
            ulonglong2 kA = Kp[l], kB = Kp[32 + l];
            ulonglong2 vA = Vp[l], vB = Vp[32 + l];
            u64p raa = 0ull, rab = 0ull, rba = 0ull, rbb = 0ull;
            uint32_t a0 = memb + (uint32_t)((w*RPW*64 + l) << 4);
            #pragma unroll
            for (int i = 0; i < RPW; i++){
                int s = w * RPW + i;
                u64p rws2 = pk1(rw[s]);
                u64p p2   = pk1(pc[s]);
                u64p rc2  = pk1(rc[s]);
                u64p m0a, m0b, m1a, m1b;
                lds2(m0a, m0b, a0);
                lds2(m1a, m1b, a0 + 512);
                // read_v partial (old mem)
                raa = fma2(rws2, m0a, raa); rab = fma2(rws2, m0b, rab);
                rba = fma2(rws2, m1a, rba); rbb = fma2(rws2, m1b, rbb);
                // update: n = pc*m + rc*v   (mask folded into pc/rc)
                u64p n0a = fma2(p2, m0a, mul2(rc2, vA.x));
                u64p n0b = fma2(p2, m0b, mul2(rc2, vA.y));
                u64p n1a = fma2(p2, m1a, mul2(rc2, vB.x));
                u64p n1b = fma2(p2, m1b, mul2(rc2, vB.y));
                sts2(a0,       n0a, n0b);
                sts2(a0 + 512, n1a, n1b);
                // dots/norm of new mem
                u64p dqp = fma2(n0b, qA.y, mul2(n0a, qA.x));
                dqp = fma2(n1a, qB.x, dqp); dqp = fma2(n1b, qB.y, dqp);
                u64p dkp = fma2(n0b, kA.y, mul2(n0a, kA.x));
                dkp = fma2(n1a, kB.x, dkp); dkp = fma2(n1b, kB.y, dkp);
                u64p nnp = fma2(n0b, n0b, mul2(n0a, n0a));
                nnp = fma2(n1a, n1a, nnp); nnp = fma2(n1b, n1b, nnp);
                float dq = wredsum(hsum2(dqp));
                float dk = wredsum(hsum2(dkp));
                float nn = wredsum(hsum2(nnp));
                if (l == 0){ dotq[s] = dq; dotk[s] = dk; nrm[s] = nn; }
                a0 += 1024;
            }
            uint32_t ra0 = readpb + (uint32_t)(w*1024 + (l << 4));
            sts2(ra0,       raa, rab);
            sts2(ra0 + 512, rba, rbb);
        }
        __syncthreads();
    }
    // epilogue: read_v for t = L-1
    if (tid < D_){
        int d = tid;
        float acc = 0.f;
        #pragma unroll
        for (int j = 0; j < NW; j++) acc += readp[j*D_ + d];
        out[(size_t)(b*L_ + (L_-1))*D_ + d] = acc;
    }
}

// ---------------- launch ----------------
extern "C" void kernel_launch(void* const* d_in, const int* in_sizes, int n_in,
                              void* d_out, int out_size)
{
    const float* init_memory = (const float*)d_in[0];
    const float* hidden      = (const float*)d_in[1];
    const float* masks       = (const float*)d_in[2];
    const float* Wq = (const float*)d_in[3];
    const float* bq = (const float*)d_in[4];
    const float* Wk = (const float*)d_in[5];
    const float* bk = (const float*)d_in[6];
    const float* Wv = (const float*)d_in[7];
    const float* bv = (const float*)d_in[8];
    const float* Wg = (const float*)d_in[9];
    const float* bg = (const float*)d_in[10];
    float* out = (float*)d_out;

    float *Qp, *Kp, *Vp;
    cudaGetSymbolAddress((void**)&Qp, g_Q);
    cudaGetSymbolAddress((void**)&Kp, g_K);
    cudaGetSymbolAddress((void**)&Vp, g_V);

    dim3 ggrid(M_/64, D_/64);
    gemm_nt<<<ggrid, 256>>>(hidden, Wq, bq, Qp);
    gemm_nt<<<ggrid, 256>>>(hidden, Wk, bk, Kp);
    gemm_nt<<<ggrid, 256>>>(hidden, Wv, bv, Vp);
    gate_kernel<<<M_*32/256, 256>>>(hidden, Wg, bg);
    invnorm_kernel<<<M_*32/256, 256>>>();

    size_t smem_bytes = (size_t)(S_*D_ + 6*S_ + 16*D_) * sizeof(float);
    cudaFuncSetAttribute(recur_kernel, cudaFuncAttributeMaxDynamicSharedMemorySize,
                         (int)smem_bytes);
    recur_kernel<<<B_, 512, smem_bytes>>>(init_memory, masks, out);

    sp_kernel<<<1, 512>>>(out, out_size);
}